// round 2
// baseline (speedup 1.0000x reference)
#include <cuda_runtime.h>
#include <cuda_bf16.h>

// Problem constants
#define Bn    8
#define Tn    32
#define DIN   768
#define DSAE  8192
#define TOPK  64
#define MROWS 256          // B*T
// Output layout (tuple order): [loss(1) | x_hat(B*T*DIN) | z(B*T*DSAE)]
#define XHAT_ELEMS (MROWS * DIN)
#define Z_ELEMS    ((size_t)MROWS * DSAE)

#define XS_STRIDE 260      // multiple of 4 -> float4-aligned rows; 260%32==4 banks

// ---------------- scratch (no allocations allowed) ----------------
__device__ float g_pre[(size_t)MROWS * DSAE];   // 8 MB
__device__ int   g_idx[MROWS * TOPK];
__device__ float g_val[MROWS * TOPK];
__device__ int   g_cnt[MROWS];
__device__ float g_rowloss[MROWS];

// =====================================================================
// Kernel 1: pre = causal-conv GEMM.  Grid: 128 blocks (s-tiles of 64),
// 256 threads. Block tile M=256 x N=64, thread tile 8(b) x 8(j).
// xs smem: x[d-chunk 16][t 32][b 8]  (row stride XS_STRIDE, float4-aligned)
// Ws smem: double-buffered [2][16][64], LDG prefetched into registers.
// =====================================================================
__global__ __launch_bounds__(256) void pre_gemm_kernel(
    const float* __restrict__ x,       // (B,T,DIN)
    const float* __restrict__ W,       // (T,DIN,DSAE)
    const float* __restrict__ b_enc)   // (DSAE)
{
    __shared__ float xs[16 * XS_STRIDE];
    __shared__ float Ws[2][16 * 64];     // [buf][dd*64 + j]

    const int tid  = threadIdx.x;
    const int s0   = blockIdx.x * 64;
    const int w    = tid >> 5;
    const int lane = tid & 31;
    const int r    = lane & 3;
    const int jth  = lane >> 2;
    const int t    = w * 4 + r;          // this thread's time index (fixed)
    const int j0   = jth * 8;

    // xs loader mapping: 256 threads load 16x32x8 = 4096 floats per chunk
    const int ldd = tid & 15;            // dd
    const int rr  = tid >> 4;            // 0..15
    const int lb  = rr >> 1;             // b 0..7
    const int tph = (rr & 1) * 16;       // t half

    // Ws loader mapping
    const int wdd = tid >> 4;            // 0..15
    const int wc4 = (tid & 15) * 4;      // column (float4)

    float acc[8][8];
#pragma unroll
    for (int i = 0; i < 8; ++i)
#pragma unroll
        for (int j = 0; j < 8; ++j) acc[i][j] = 0.f;

    for (int d0 = 0; d0 < DIN; d0 += 16) {
        __syncthreads();   // protect xs from overwrite
        // ---- load x chunk into xs ----
        {
            const float* xp = x + lb * (Tn * DIN) + d0 + ldd;
#pragma unroll
            for (int q = 0; q < 16; ++q) {
                const int tp = tph + q;
                xs[ldd * XS_STRIDE + tp * 8 + lb] = xp[tp * DIN];
            }
        }
        // ---- prefetch W for off=0 ----
        float4 wreg = *reinterpret_cast<const float4*>(
            W + (size_t)(0 * DIN + d0 + wdd) * DSAE + s0 + wc4);
        __syncthreads();   // xs ready

        for (int off = 0; off < Tn; ++off) {
            const int buf = off & 1;
            *reinterpret_cast<float4*>(&Ws[buf][wdd * 64 + wc4]) = wreg;
            __syncthreads();   // Ws[buf] ready (and prev buf reads done)

            if (off < Tn - 1) {   // prefetch next W slab (hidden under compute)
                wreg = *reinterpret_cast<const float4*>(
                    W + (size_t)((off + 1) * DIN + d0 + wdd) * DSAE + s0 + wc4);
            }

            if (t >= off) {
                const int tp8 = (t - off) * 8;
                const float* wsp = Ws[buf];
#pragma unroll
                for (int dd = 0; dd < 16; ++dd) {
                    const float4 xa = *reinterpret_cast<const float4*>(&xs[dd * XS_STRIDE + tp8]);
                    const float4 xb = *reinterpret_cast<const float4*>(&xs[dd * XS_STRIDE + tp8 + 4]);
                    const float4 wa = *reinterpret_cast<const float4*>(&wsp[dd * 64 + j0]);
                    const float4 wb = *reinterpret_cast<const float4*>(&wsp[dd * 64 + j0 + 4]);
                    const float xv[8] = {xa.x, xa.y, xa.z, xa.w, xb.x, xb.y, xb.z, xb.w};
                    const float wv[8] = {wa.x, wa.y, wa.z, wa.w, wb.x, wb.y, wb.z, wb.w};
#pragma unroll
                    for (int i = 0; i < 8; ++i)
#pragma unroll
                        for (int j = 0; j < 8; ++j)
                            acc[i][j] = fmaf(xv[i], wv[j], acc[i][j]);
                }
            }
        }
    }

    // ---- epilogue: add b_enc, write g_pre ----
    float be[8];
#pragma unroll
    for (int j = 0; j < 8; ++j) be[j] = b_enc[s0 + j0 + j];

#pragma unroll
    for (int i = 0; i < 8; ++i) {            // i == b
        const int row = i * Tn + t;          // row = b*T + t
        float* outp = g_pre + (size_t)row * DSAE + s0 + j0;
        float4 o0, o1;
        o0.x = acc[i][0] + be[0]; o0.y = acc[i][1] + be[1];
        o0.z = acc[i][2] + be[2]; o0.w = acc[i][3] + be[3];
        o1.x = acc[i][4] + be[4]; o1.y = acc[i][5] + be[5];
        o1.z = acc[i][6] + be[6]; o1.w = acc[i][7] + be[7];
        *reinterpret_cast<float4*>(outp)     = o0;
        *reinterpret_cast<float4*>(outp + 4) = o1;
    }
}

// =====================================================================
// Kernel 2: per-row exact TopK via 4-pass radix select on order-preserving
// uint keys, then deterministic prefix-sum compaction.
// One block per (b,t) row, 256 threads.
// =====================================================================
__global__ __launch_bounds__(256) void topk_kernel(float* __restrict__ z_out)
{
    const int row = blockIdx.x;
    const int tid = threadIdx.x;

    __shared__ unsigned us[DSAE];       // 32 KB
    __shared__ unsigned hist[256];
    __shared__ unsigned s_prefix;
    __shared__ int      s_k;
    __shared__ int      cnts[256];

    const float* rp = g_pre + (size_t)row * DSAE;

    for (int j = tid; j < DSAE; j += 256) {
        unsigned u = __float_as_uint(rp[j]);
        u = (u & 0x80000000u) ? ~u : (u | 0x80000000u);   // monotone key
        us[j] = u;
    }
    if (tid == 0) { s_prefix = 0u; s_k = TOPK; }
    __syncthreads();

    for (int p = 24; p >= 0; p -= 8) {
        hist[tid] = 0u;
        __syncthreads();
        const unsigned pref = s_prefix;
        const int shift_hi = p + 8;
        for (int j = tid; j < DSAE; j += 256) {
            const unsigned u = us[j];
            const bool match = (shift_hi >= 32) || (((u ^ pref) >> shift_hi) == 0u);
            if (match) atomicAdd(&hist[(u >> p) & 255u], 1u);
        }
        __syncthreads();
        if (tid == 0) {
            int k = s_k;
            unsigned c = 0;
            for (int bin = 255; bin >= 0; --bin) {
                const unsigned h = hist[bin];
                if (c + h >= (unsigned)k) {
                    s_prefix = pref | ((unsigned)bin << p);
                    s_k = k - (int)c;
                    break;
                }
                c += h;
            }
        }
        __syncthreads();
    }

    const unsigned T = s_prefix;   // exact key of the K-th largest value

    // select: top-K AND strictly positive (relu kills the rest)
    int cnt = 0;
#pragma unroll 4
    for (int j = 0; j < DSAE / 256; ++j) {
        const unsigned u = us[tid + j * 256];
        if (u >= T && u > 0x80000000u) cnt++;
    }
    cnts[tid] = cnt;
    __syncthreads();
    if (tid == 0) {
        int run = 0;
        for (int i = 0; i < 256; ++i) { const int c = cnts[i]; cnts[i] = run; run += c; }
        g_cnt[row] = (run > TOPK) ? TOPK : run;
    }
    __syncthreads();

    int pos = cnts[tid];
    for (int j = 0; j < DSAE / 256; ++j) {
        const int sidx = tid + j * 256;
        const unsigned u = us[sidx];
        if (u >= T && u > 0x80000000u) {
            const float v = rp[sidx];   // positive by construction
            if (pos < TOPK) {
                g_idx[row * TOPK + pos] = sidx;
                g_val[row * TOPK + pos] = v;
            }
            z_out[(size_t)row * DSAE + sidx] = v;
            pos++;
        }
    }
}

// =====================================================================
// Kernel 3: sparse decode x_hat = z @ W_dec + b_dec, fused per-row loss.
// One block per row, 256 threads, 3 columns each.
// =====================================================================
__global__ __launch_bounds__(256) void decode_kernel(
    const float* __restrict__ x,
    const float* __restrict__ W_dec,    // (DSAE, DIN)
    const float* __restrict__ b_dec,
    float* __restrict__ xhat)
{
    const int row = blockIdx.x;
    const int tid = threadIdx.x;

    __shared__ float sval[TOPK];
    __shared__ int   sidx[TOPK];
    __shared__ float red[256];

    const int cnt = g_cnt[row];
    if (tid < TOPK) {
        sval[tid] = (tid < cnt) ? g_val[row * TOPK + tid] : 0.f;
        sidx[tid] = (tid < cnt) ? g_idx[row * TOPK + tid] : 0;
    }
    __syncthreads();

    float a0 = b_dec[tid];
    float a1 = b_dec[tid + 256];
    float a2 = b_dec[tid + 512];

    for (int kk = 0; kk < cnt; ++kk) {
        const float v = sval[kk];
        const float* wd = W_dec + (size_t)sidx[kk] * DIN;
        a0 = fmaf(v, wd[tid],       a0);
        a1 = fmaf(v, wd[tid + 256], a1);
        a2 = fmaf(v, wd[tid + 512], a2);
    }

    const size_t base = (size_t)row * DIN;
    xhat[base + tid]       = a0;
    xhat[base + tid + 256] = a1;
    xhat[base + tid + 512] = a2;

    const float d0 = a0 - x[base + tid];
    const float d1 = a1 - x[base + tid + 256];
    const float d2 = a2 - x[base + tid + 512];
    red[tid] = d0 * d0 + d1 * d1 + d2 * d2;
    __syncthreads();
#pragma unroll
    for (int st = 128; st > 0; st >>= 1) {
        if (tid < st) red[tid] += red[tid + st];
        __syncthreads();
    }
    if (tid == 0) g_rowloss[row] = red[0];
}

// =====================================================================
// Kernel 4: deterministic final loss reduction.
// =====================================================================
__global__ __launch_bounds__(256) void loss_kernel(float* __restrict__ loss_out)
{
    const int tid = threadIdx.x;
    __shared__ float red[256];
    red[tid] = g_rowloss[tid];
    __syncthreads();
#pragma unroll
    for (int st = 128; st > 0; st >>= 1) {
        if (tid < st) red[tid] += red[tid + st];
        __syncthreads();
    }
    if (tid == 0) loss_out[0] = red[0] * (1.0f / MROWS);
}

// =====================================================================
extern "C" void kernel_launch(void* const* d_in, const int* in_sizes, int n_in,
                              void* d_out, int out_size)
{
    const float* x      = (const float*)d_in[0];
    const float* W_enc  = (const float*)d_in[1];
    const float* W_dec  = (const float*)d_in[2];
    const float* b_enc  = (const float*)d_in[3];
    const float* b_dec  = (const float*)d_in[4];

    float* out   = (float*)d_out;
    float* loss  = out;                    // [0]
    float* xhat  = out + 1;                // [1 .. 1+196608)
    float* z     = out + 1 + XHAT_ELEMS;   // [.. end)

    // z is sparse: zero the region (d_out is poisoned with 0xAA)
    cudaMemsetAsync(z, 0, Z_ELEMS * sizeof(float));

    pre_gemm_kernel<<<DSAE / 64, 256>>>(x, W_enc, b_enc);
    topk_kernel<<<MROWS, 256>>>(z);
    decode_kernel<<<MROWS, 256>>>(x, W_dec, b_dec, xhat);
    loss_kernel<<<1, 256>>>(loss);
}